// round 11
// baseline (speedup 1.0000x reference)
#include <cuda_runtime.h>
#include <math.h>

#define T_LEN 128
#define F_DIM 16

// Band kernel H: [7 classes][5 taps][16 f][16 o]
__device__ __align__(16) float g_H[7 * 5 * 16 * 16];

__device__ __forceinline__ void fma2(unsigned long long& acc,
                                     unsigned long long a2,
                                     unsigned long long b2) {
    asm("fma.rn.f32x2 %0, %1, %2, %0;" : "+l"(acc) : "l"(a2), "l"(b2));
}

// ---------------------------------------------------------------------------
// Kernel 1 (merged): build lap params, sigma_max via modal decomposition
// (exact: max over temporal modes is at lam = +/-2cos(pi/129) by convexity),
// 16-step Lanczos on EXPLICIT B = A^T A (one matvec/iter), Sturm bisection,
// then build band kernel H by unit-vector probing (560 tasks, 512 threads).
// ---------------------------------------------------------------------------
__global__ void __launch_bounds__(512) setup_build_kernel(
    const float* __restrict__ adj, const float* __restrict__ weight) {
    __shared__ float sAhat[16][16];
    __shared__ float sMi[16][16], sMb[16][16];
    __shared__ float sA[2][16][16];   // sA[h][k][i] = A_h[k][i]
    __shared__ float sB[2][16][16];   // B_h = A_h^T A_h
    __shared__ float seii[16], sebi[16], spb[16], spi[16];
    __shared__ float sc;
    __shared__ float AiT[16][16], AbT[16][16];   // (c*M - I)^T
    __shared__ float AiC[16][16], AbC[16][16];   // column copies
    __shared__ float cei[16], ceb[16];
    __shared__ float W[3][16][16];

    const int tid = threadIdx.x;

    // ---- Ahat + weights ----
    if (tid < 256) {
        int f = tid >> 4, g = tid & 15;
        sAhat[f][g] = (f == g) ? 1.0f : 1.0f / (1.0f + expf(-adj[tid]));
    }
    for (int i = tid; i < 768; i += 512) ((float*)W)[i] = weight[i];
    __syncthreads();

    // ---- degrees ----
    if (tid < 16) {
        float a = 0.0f;
        #pragma unroll
        for (int g = 0; g < 16; g++) a += sAhat[tid][g];
        spb[tid] = rsqrtf(a + 1.0f);
        spi[tid] = rsqrtf(a + 2.0f);
    }
    __syncthreads();

    // ---- lap blocks ----
    if (tid < 256) {
        int f = tid >> 4, g = tid & 15;
        float diag = (f == g) ? 1.0f : 0.0f;
        sMi[f][g] = diag - spi[f] * sAhat[f][g] * spi[g];
        sMb[f][g] = diag - spb[f] * sAhat[f][g] * spb[g];
    }
    if (tid < 16) {
        seii[tid] = -spi[tid] * spi[tid];
        sebi[tid] = -spb[tid] * spi[tid];
    }
    __syncthreads();

    // ---- A_h = Mi + lam_h * diag(eii), lam_h = +/-2cos(pi/129) ----
    {
        int h = tid >> 8, idx = tid & 255;
        int k = idx >> 4, i = idx & 15;
        float lam = (h ? -2.0f : 2.0f) * cosf(3.14159265358979f / 129.0f);
        sA[h][k][i] = sMi[k][i] + ((k == i) ? lam * seii[k] : 0.0f);
    }
    __syncthreads();

    // ---- B_h = A_h^T A_h (explicit 16x16, parallel) ----
    {
        int h = tid >> 8, idx = tid & 255;
        int i = idx >> 4, j = idx & 15;
        float acc = 0.0f;
        #pragma unroll
        for (int k = 0; k < 16; k++) acc += sA[h][k][i] * sA[h][k][j];
        sB[h][i][j] = acc;
    }
    __syncthreads();

    // ---- warp 0: exact 16-step Lanczos on B (one matvec/iter) + Sturm ----
    if (tid < 32) {
        const int lane = tid;
        const int half = lane >> 4;
        const int f    = lane & 15;
        const int base = half << 4;

        float Mr[16];
        #pragma unroll
        for (int g = 0; g < 16; g++) Mr[g] = sB[half][f][g];

        float v, vp = 0.0f;
        {
            unsigned h = (unsigned)(f * 2654435761u) + 0x9E3779B9u;
            h ^= h >> 15; h *= 0x2C1B3C6Du; h ^= h >> 12; h *= 0x297A2D39u; h ^= h >> 15;
            v = (float)(h & 0xFFFFFFu) * (1.0f / 16777216.0f) - 0.5f + 0.03f * (float)f;
            float nn = v * v;
            #pragma unroll
            for (int o = 8; o > 0; o >>= 1) nn += __shfl_xor_sync(0xFFFFFFFFu, nn, o);
            v *= rsqrtf(nn);
        }

        float al[16], be[16];
        float bprev = 0.0f;
        #pragma unroll
        for (int it = 0; it < 16; it++) {
            float w = 0.0f;
            #pragma unroll
            for (int g = 0; g < 16; g++)
                w += Mr[g] * __shfl_sync(0xFFFFFFFFu, v, base + g);
            float pa = v * w;
            #pragma unroll
            for (int o = 8; o > 0; o >>= 1) pa += __shfl_xor_sync(0xFFFFFFFFu, pa, o);
            float alpha = pa;
            w -= alpha * v + bprev * vp;
            float ps = w * w;
            #pragma unroll
            for (int o = 8; o > 0; o >>= 1) ps += __shfl_xor_sync(0xFFFFFFFFu, ps, o);
            float beta = sqrtf(ps);
            al[it] = alpha; be[it] = beta;
            float rb = (beta > 1e-30f) ? 1.0f / beta : 0.0f;
            vp = v; v = w * rb;
            bprev = beta;
        }

        float lo = 0.0f, hi = 8.0f;
        for (int r = 0; r < 6; r++) {
            float x = lo + (hi - lo) * (float)(f + 1) * (1.0f / 17.0f);
            int cnt = 0;
            float d = al[0] - x;
            if (d < 0.0f) cnt++;
            #pragma unroll
            for (int i = 1; i < 16; i++) {
                float dd = (fabsf(d) < 1e-25f) ? ((d < 0.0f) ? -1e-25f : 1e-25f) : d;
                d = (al[i] - x) - (be[i - 1] * be[i - 1]) / dd;
                if (d < 0.0f) cnt++;
            }
            bool ge = (cnt < 16);
            unsigned m = (__ballot_sync(0xFFFFFFFFu, ge) >> (half << 4)) & 0xFFFFu;
            int nge = __popc(m);
            float w17 = (hi - lo) * (1.0f / 17.0f);
            lo = lo + w17 * (float)nge;
            hi = lo + w17;
        }
        float lmax = 0.5f * (lo + hi);
        float other = __shfl_sync(0xFFFFFFFFu, lmax, lane ^ 16);
        lmax = fmaxf(lmax, other);
        if (lane == 0) sc = 2.0f / sqrtf(lmax);
    }
    __syncthreads();

    // ---- scaled operator blocks for H probing ----
    const float c = sc;
    if (tid < 256) {
        int f = tid >> 4, g = tid & 15;
        float diag = (f == g) ? 1.0f : 0.0f;
        float vi = c * sMi[f][g] - diag;
        float vb = c * sMb[f][g] - diag;
        AiT[g][f] = vi;  AbT[g][f] = vb;
        AiC[f][g] = vi;  AbC[f][g] = vb;
    }
    if (tid < 16) {
        cei[tid] = c * seii[tid];
        ceb[tid] = c * sebi[tid];
    }
    __syncthreads();

    // ---- build H by unit-vector probing (verified exact in R10) ----
    const int reps[7] = {0, 1, 2, 3, 125, 126, 127};
    for (int task = tid; task < 560; task += 512) {
        const int f    = task & 15;
        const int rest = task >> 4;
        const int dt   = rest % 5;
        const int cls  = rest / 5;
        const int ts   = reps[cls];
        const int p    = ts + dt - 2;

        float Hrow[16];
        if (p < 0 || p > 127) {
            #pragma unroll
            for (int o = 0; o < 16; o++) Hrow[o] = 0.0f;
        } else {
            float y1w[3][16];
            #pragma unroll
            for (int si = 0; si < 3; si++) {
                int s = ts - 1 + si;
                #pragma unroll
                for (int r = 0; r < 16; r++) y1w[si][r] = 0.0f;
                if (s < 0 || s > 127) continue;
                bool sbnd = (s == 0 || s == 127);
                if (s == p) {
                    const float* col = sbnd ? &AbC[f][0] : &AiC[f][0];
                    #pragma unroll
                    for (int r = 0; r < 16; r++) y1w[si][r] = col[r];
                }
                if (s - 1 == p) {
                    const float* el = (s == 1 || s == 127) ? ceb : cei;
                    y1w[si][f] += el[f];
                }
                if (s + 1 == p) {
                    const float* er = (s == 0 || s == 126) ? ceb : cei;
                    y1w[si][f] += er[f];
                }
            }
            bool tb = (ts == 0 || ts == 127);
            float y2[16];
            #pragma unroll
            for (int r = 0; r < 16; r++) {
                const float* AR = tb ? &AbT[r][0] : &AiT[r][0];
                float acc = 0.0f;
                #pragma unroll
                for (int g = 0; g < 16; g++) acc += AR[g] * y1w[1][g];
                if (ts > 0) {
                    const float* el = (ts == 1 || ts == 127) ? ceb : cei;
                    acc += el[r] * y1w[0][r];
                }
                if (ts < 127) {
                    const float* er = (ts == 0 || ts == 126) ? ceb : cei;
                    acc += er[r] * y1w[2][r];
                }
                float y0r = (ts == p && r == f) ? 1.0f : 0.0f;
                y2[r] = 2.0f * acc - y0r;
            }
            #pragma unroll
            for (int o = 0; o < 16; o++) {
                float h = (ts == p) ? W[0][f][o] : 0.0f;
                #pragma unroll
                for (int r = 0; r < 16; r++)
                    h += y1w[1][r] * W[1][r][o] + y2[r] * W[2][r][o];
                Hrow[o] = h;
            }
        }
        #pragma unroll
        for (int o = 0; o < 16; o++) g_H[task * 16 + o] = Hrow[o];
    }
}

// ---------------------------------------------------------------------------
// Kernel 2: main = 5-tap band GEMM with packed f32x2 FMA.
// One block per batch row, thread t. Interior-class H staged in shared (5KB);
// the 6 boundary threads read their H class from global (L1-cached) through a
// generic pointer. Single barrier. out = sum_dt x[t+dt-2] * H[cls][dt] + bias.
// ---------------------------------------------------------------------------
__global__ void __launch_bounds__(128) sgconv_main_kernel(
    const float* __restrict__ x, const float* __restrict__ bias,
    float* __restrict__ out) {
    __shared__ __align__(16) float sHi[1280];   // interior class (cls=3)
    __shared__ __align__(16) float xT[132][20]; // rows 2..129 = t 0..127
    __shared__ __align__(16) float sb[16];

    const int t = threadIdx.x;

    // stage interior H (320 float4)
    {
        const float4* src = (const float4*)(g_H + 3 * 1280);
        float4* dst = (float4*)sHi;
        dst[t] = src[t];
        dst[t + 128] = src[t + 128];
        if (t < 64) dst[t + 256] = src[t + 256];
    }
    if (t < 2) {
        float4 z = make_float4(0.f, 0.f, 0.f, 0.f);
        float4* p0 = (float4*)&xT[t][0];
        float4* p1 = (float4*)&xT[130 + t][0];
        p0[0] = z; p0[1] = z; p0[2] = z; p0[3] = z;
        p1[0] = z; p1[1] = z; p1[2] = z; p1[3] = z;
    }
    if (t < 16) sb[t] = bias[t];
    {
        const float4* xb = (const float4*)(x + (size_t)blockIdx.x * 2048 + t * 16);
        float4* dst = (float4*)&xT[t + 2][0];
        dst[0] = xb[0]; dst[1] = xb[1]; dst[2] = xb[2]; dst[3] = xb[3];
    }
    __syncthreads();   // the only barrier

    const int cls = (t <= 2) ? t : ((t >= 125) ? (t - 121) : 3);
    const ulonglong2* Hc = (cls == 3) ? (const ulonglong2*)sHi
                                      : (const ulonglong2*)(g_H + cls * 1280);

    // accumulators as 8 packed pairs, init from bias
    unsigned long long ov2[8];
    {
        const ulonglong2* b2 = (const ulonglong2*)sb;
        ulonglong2 b01 = b2[0], b23 = b2[1], b45 = b2[2], b67 = b2[3];
        ov2[0] = b01.x; ov2[1] = b01.y; ov2[2] = b23.x; ov2[3] = b23.y;
        ov2[4] = b45.x; ov2[5] = b45.y; ov2[6] = b67.x; ov2[7] = b67.y;
    }

    #pragma unroll
    for (int dt = 0; dt < 5; dt++) {
        const float4* xr = (const float4*)&xT[t + dt][0];
        float4 x0 = xr[0], x1 = xr[1], x2 = xr[2], x3 = xr[3];
        float xw[16] = { x0.x, x0.y, x0.z, x0.w,  x1.x, x1.y, x1.z, x1.w,
                         x2.x, x2.y, x2.z, x2.w,  x3.x, x3.y, x3.z, x3.w };
        const ulonglong2* Hd = Hc + dt * 64;   // 256 floats = 64 ulonglong2
        #pragma unroll
        for (int f = 0; f < 16; f++) {
            unsigned long long a2;
            asm("mov.b64 %0, {%1, %1};" : "=l"(a2) : "r"(__float_as_uint(xw[f])));
            ulonglong2 hA = Hd[f * 4 + 0];
            ulonglong2 hB = Hd[f * 4 + 1];
            ulonglong2 hC = Hd[f * 4 + 2];
            ulonglong2 hD = Hd[f * 4 + 3];
            fma2(ov2[0], a2, hA.x); fma2(ov2[1], a2, hA.y);
            fma2(ov2[2], a2, hB.x); fma2(ov2[3], a2, hB.y);
            fma2(ov2[4], a2, hC.x); fma2(ov2[5], a2, hC.y);
            fma2(ov2[6], a2, hD.x); fma2(ov2[7], a2, hD.y);
        }
    }

    ulonglong2* ob = (ulonglong2*)(out + (size_t)blockIdx.x * 2048 + t * 16);
    ulonglong2 s0, s1, s2, s3;
    s0.x = ov2[0]; s0.y = ov2[1];
    s1.x = ov2[2]; s1.y = ov2[3];
    s2.x = ov2[4]; s2.y = ov2[5];
    s3.x = ov2[6]; s3.y = ov2[7];
    ob[0] = s0; ob[1] = s1; ob[2] = s2; ob[3] = s3;
}

extern "C" void kernel_launch(void* const* d_in, const int* in_sizes, int n_in,
                              void* d_out, int out_size) {
    const float* x      = (const float*)d_in[0];  // [1024,128,16]
    const float* weight = (const float*)d_in[1];  // [3,16,16]
    const float* bias   = (const float*)d_in[2];  // [16]
    const float* adj    = (const float*)d_in[3];  // [16,16]
    int batch = in_sizes[0] / (T_LEN * F_DIM);

    setup_build_kernel<<<1, 512>>>(adj, weight);
    sgconv_main_kernel<<<batch, 128>>>(x, bias, (float*)d_out);
}

// round 12
// speedup vs baseline: 1.8017x; 1.8017x over previous
#include <cuda_runtime.h>
#include <math.h>

#define T_LEN 128
#define F_DIM 16

// Exports from setup: unscaled lap blocks/edges + combined weights G.
__device__ __align__(16) float g_Mi[256];   // interior diag block, row-major M[g][r]
__device__ __align__(16) float g_Mb[256];   // boundary diag block (t=0,127)
__device__ __align__(16) float g_eii[16];   // interior temporal coupling (unscaled)
__device__ __align__(16) float g_ebi[16];   // boundary temporal coupling (unscaled)
__device__ __align__(16) float g_G[768];    // G0 = W0-W1+W2 ; G1 = c(W1-4W2) ; G2 = 2c^2 W2

__device__ __forceinline__ void fma2(unsigned long long& acc,
                                     unsigned long long a2,
                                     unsigned long long b2) {
    asm("fma.rn.f32x2 %0, %1, %2, %0;" : "+l"(acc) : "l"(a2), "l"(b2));
}
__device__ __forceinline__ unsigned long long splat2(float v) {
    unsigned long long a2;
    asm("mov.b64 %0, {%1, %1};" : "=l"(a2) : "r"(__float_as_uint(v)));
    return a2;
}

// ---------------------------------------------------------------------------
// Kernel 1: build lap params, sigma_max via modal decomposition (exact: max
// over temporal modes at lam = +/-2cos(pi/129) by convexity), 16-step Lanczos
// on explicit B = A^T A, grid Sturm bisection; then export blocks + G.
// ---------------------------------------------------------------------------
__global__ void __launch_bounds__(512) setup_kernel(
    const float* __restrict__ adj, const float* __restrict__ weight) {
    __shared__ float sAhat[16][16];
    __shared__ float sMi[16][16], sMb[16][16];
    __shared__ float sA[2][16][16];
    __shared__ float sB[2][16][16];
    __shared__ float seii[16], sebi[16], spb[16], spi[16];
    __shared__ float sc;

    const int tid = threadIdx.x;

    if (tid < 256) {
        int f = tid >> 4, g = tid & 15;
        sAhat[f][g] = (f == g) ? 1.0f : 1.0f / (1.0f + expf(-adj[tid]));
    }
    __syncthreads();

    if (tid < 16) {
        float a = 0.0f;
        #pragma unroll
        for (int g = 0; g < 16; g++) a += sAhat[tid][g];
        spb[tid] = rsqrtf(a + 1.0f);
        spi[tid] = rsqrtf(a + 2.0f);
    }
    __syncthreads();

    if (tid < 256) {
        int f = tid >> 4, g = tid & 15;
        float diag = (f == g) ? 1.0f : 0.0f;
        sMi[f][g] = diag - spi[f] * sAhat[f][g] * spi[g];
        sMb[f][g] = diag - spb[f] * sAhat[f][g] * spb[g];
    }
    if (tid < 16) {
        seii[tid] = -spi[tid] * spi[tid];
        sebi[tid] = -spb[tid] * spi[tid];
    }
    __syncthreads();

    // A_h = Mi + lam_h * diag(eii), lam_h = +/-2cos(pi/129)
    {
        int h = tid >> 8, idx = tid & 255;
        int k = idx >> 4, i = idx & 15;
        float lam = (h ? -2.0f : 2.0f) * cosf(3.14159265358979f / 129.0f);
        sA[h][k][i] = sMi[k][i] + ((k == i) ? lam * seii[k] : 0.0f);
    }
    __syncthreads();

    // B_h = A_h^T A_h
    {
        int h = tid >> 8, idx = tid & 255;
        int i = idx >> 4, j = idx & 15;
        float acc = 0.0f;
        #pragma unroll
        for (int k = 0; k < 16; k++) acc += sA[h][k][i] * sA[h][k][j];
        sB[h][i][j] = acc;
    }
    __syncthreads();

    // warp 0: exact 16-step Lanczos on B + grid Sturm bisection
    if (tid < 32) {
        const int lane = tid;
        const int half = lane >> 4;
        const int f    = lane & 15;
        const int base = half << 4;

        float Mr[16];
        #pragma unroll
        for (int g = 0; g < 16; g++) Mr[g] = sB[half][f][g];

        float v, vp = 0.0f;
        {
            unsigned h = (unsigned)(f * 2654435761u) + 0x9E3779B9u;
            h ^= h >> 15; h *= 0x2C1B3C6Du; h ^= h >> 12; h *= 0x297A2D39u; h ^= h >> 15;
            v = (float)(h & 0xFFFFFFu) * (1.0f / 16777216.0f) - 0.5f + 0.03f * (float)f;
            float nn = v * v;
            #pragma unroll
            for (int o = 8; o > 0; o >>= 1) nn += __shfl_xor_sync(0xFFFFFFFFu, nn, o);
            v *= rsqrtf(nn);
        }

        float al[16], be[16];
        float bprev = 0.0f;
        #pragma unroll
        for (int it = 0; it < 16; it++) {
            float w = 0.0f;
            #pragma unroll
            for (int g = 0; g < 16; g++)
                w += Mr[g] * __shfl_sync(0xFFFFFFFFu, v, base + g);
            float pa = v * w;
            #pragma unroll
            for (int o = 8; o > 0; o >>= 1) pa += __shfl_xor_sync(0xFFFFFFFFu, pa, o);
            float alpha = pa;
            w -= alpha * v + bprev * vp;
            float ps = w * w;
            #pragma unroll
            for (int o = 8; o > 0; o >>= 1) ps += __shfl_xor_sync(0xFFFFFFFFu, ps, o);
            float beta = sqrtf(ps);
            al[it] = alpha; be[it] = beta;
            float rb = (beta > 1e-30f) ? 1.0f / beta : 0.0f;
            vp = v; v = w * rb;
            bprev = beta;
        }

        float lo = 0.0f, hi = 8.0f;
        for (int r = 0; r < 6; r++) {
            float x = lo + (hi - lo) * (float)(f + 1) * (1.0f / 17.0f);
            int cnt = 0;
            float d = al[0] - x;
            if (d < 0.0f) cnt++;
            #pragma unroll
            for (int i = 1; i < 16; i++) {
                float dd = (fabsf(d) < 1e-25f) ? ((d < 0.0f) ? -1e-25f : 1e-25f) : d;
                d = (al[i] - x) - (be[i - 1] * be[i - 1]) / dd;
                if (d < 0.0f) cnt++;
            }
            bool ge = (cnt < 16);
            unsigned m = (__ballot_sync(0xFFFFFFFFu, ge) >> (half << 4)) & 0xFFFFu;
            int nge = __popc(m);
            float w17 = (hi - lo) * (1.0f / 17.0f);
            lo = lo + w17 * (float)nge;
            hi = lo + w17;
        }
        float lmax = 0.5f * (lo + hi);
        float other = __shfl_sync(0xFFFFFFFFu, lmax, lane ^ 16);
        lmax = fmaxf(lmax, other);
        if (lane == 0) sc = 2.0f / sqrtf(lmax);
    }
    __syncthreads();

    // exports: unscaled blocks/edges + combined weight matrices G
    const float c = sc;
    if (tid < 256) {
        int f = tid >> 4, g = tid & 15;
        g_Mi[tid] = sMi[f][g];
        g_Mb[tid] = sMb[f][g];
        float w0 = weight[tid], w1 = weight[256 + tid], w2 = weight[512 + tid];
        g_G[tid]       = w0 - w1 + w2;
        g_G[256 + tid] = c * (w1 - 4.0f * w2);
        g_G[512 + tid] = 2.0f * c * c * w2;
    }
    if (tid < 16) {
        g_eii[tid] = seii[tid];
        g_ebi[tid] = sebi[tid];
    }
}

// ---------------------------------------------------------------------------
// Kernel 2: main. out = x G0 + (L^T x) G1 + ((L^T)^2 x) G2 + bias.
// One block per batch row, thread t = time step. Two L^T applies + one GEMM,
// all in packed f32x2 column-accumulate form; every matrix row LDS is a
// warp-uniform broadcast from shared. Two barriers.
// ---------------------------------------------------------------------------
__global__ void __launch_bounds__(128) sgconv_main_kernel(
    const float* __restrict__ x, const float* __restrict__ bias,
    float* __restrict__ out) {
    __shared__ __align__(16) float sMi[16][16], sMb[16][16];  // row-major M[g][r]
    __shared__ __align__(16) float sG[3][16][16];
    __shared__ __align__(16) float se_i[16], se_b[16];
    __shared__ __align__(16) float sb16[16];
    __shared__ __align__(16) float xsh[128][20];
    __shared__ __align__(16) float ush[128][20];

    const int t = threadIdx.x;
    const bool bnd = (t == 0 || t == 127);

    // param staging
    {
        ((float*)sMi)[t] = g_Mi[t];          ((float*)sMi)[t + 128] = g_Mi[t + 128];
        ((float*)sMb)[t] = g_Mb[t];          ((float*)sMb)[t + 128] = g_Mb[t + 128];
        #pragma unroll
        for (int r = 0; r < 6; r++) ((float*)sG)[t + r * 128] = g_G[t + r * 128];
        if (t < 16) { se_i[t] = g_eii[t]; se_b[t] = g_ebi[t]; sb16[t] = bias[t]; }
    }

    // load x row: scalars + publish packed
    float xw[16];
    {
        const float4* xb = (const float4*)(x + (size_t)blockIdx.x * 2048 + t * 16);
        float4* dst = (float4*)&xsh[t][0];
        #pragma unroll
        for (int q = 0; q < 4; q++) {
            float4 vv = xb[q];
            xw[4*q+0] = vv.x; xw[4*q+1] = vv.y; xw[4*q+2] = vv.z; xw[4*q+3] = vv.w;
            dst[q] = vv;
        }
    }
    __syncthreads();   // barrier 1: params + xsh

    // packed L^T apply: dst += M_cls^T src + e_l .* nbr[t-1] + e_r .* nbr[t+1]
    auto apply_lap = [&](const float* srcw, float (&nbr)[128][20],
                         unsigned long long (&dst)[8]) {
        #pragma unroll
        for (int q = 0; q < 8; q++) dst[q] = 0ull;   // (0.0f, 0.0f)
        if (t > 0) {
            const float* el = (t == 1 || t == 127) ? se_b : se_i;
            const ulonglong2* e2 = (const ulonglong2*)el;
            const ulonglong2* nm = (const ulonglong2*)&nbr[t - 1][0];
            #pragma unroll
            for (int q = 0; q < 4; q++) {
                ulonglong2 ee = e2[q], nn = nm[q];
                fma2(dst[2*q],   ee.x, nn.x);
                fma2(dst[2*q+1], ee.y, nn.y);
            }
        }
        if (t < 127) {
            const float* er = (t == 0 || t == 126) ? se_b : se_i;
            const ulonglong2* e2 = (const ulonglong2*)er;
            const ulonglong2* np = (const ulonglong2*)&nbr[t + 1][0];
            #pragma unroll
            for (int q = 0; q < 4; q++) {
                ulonglong2 ee = e2[q], nn = np[q];
                fma2(dst[2*q],   ee.x, nn.x);
                fma2(dst[2*q+1], ee.y, nn.y);
            }
        }
        const float (*M)[16] = bnd ? sMb : sMi;
        #pragma unroll
        for (int g = 0; g < 16; g++) {
            unsigned long long a2 = splat2(srcw[g]);
            const ulonglong2* row = (const ulonglong2*)&M[g][0];
            ulonglong2 rA = row[0], rB = row[1], rC = row[2], rD = row[3];
            fma2(dst[0], a2, rA.x); fma2(dst[1], a2, rA.y);
            fma2(dst[2], a2, rB.x); fma2(dst[3], a2, rB.y);
            fma2(dst[4], a2, rC.x); fma2(dst[5], a2, rC.y);
            fma2(dst[6], a2, rD.x); fma2(dst[7], a2, rD.y);
        }
    };

    // u1 = L^T x
    unsigned long long u12[8];
    apply_lap(xw, xsh, u12);
    float u1w[16];
    #pragma unroll
    for (int q = 0; q < 8; q++) {
        unsigned lo, hi;
        asm("mov.b64 {%0, %1}, %2;" : "=r"(lo), "=r"(hi) : "l"(u12[q]));
        u1w[2*q] = __uint_as_float(lo); u1w[2*q+1] = __uint_as_float(hi);
    }
    {
        ulonglong2* up = (ulonglong2*)&ush[t][0];
        ulonglong2 a, b;
        a.x = u12[0]; a.y = u12[1]; b.x = u12[2]; b.y = u12[3];
        up[0] = a; up[1] = b;
        a.x = u12[4]; a.y = u12[5]; b.x = u12[6]; b.y = u12[7];
        up[2] = a; up[3] = b;
    }
    __syncthreads();   // barrier 2: ush

    // u2 = L^T u1
    unsigned long long u22[8];
    apply_lap(u1w, ush, u22);
    float u2w[16];
    #pragma unroll
    for (int q = 0; q < 8; q++) {
        unsigned lo, hi;
        asm("mov.b64 {%0, %1}, %2;" : "=r"(lo), "=r"(hi) : "l"(u22[q]));
        u2w[2*q] = __uint_as_float(lo); u2w[2*q+1] = __uint_as_float(hi);
    }

    // out = x G0 + u1 G1 + u2 G2 + bias
    unsigned long long ov2[8];
    {
        const ulonglong2* b2 = (const ulonglong2*)sb16;
        ulonglong2 b01 = b2[0], b23 = b2[1], b45 = b2[2], b67 = b2[3];
        ov2[0] = b01.x; ov2[1] = b01.y; ov2[2] = b23.x; ov2[3] = b23.y;
        ov2[4] = b45.x; ov2[5] = b45.y; ov2[6] = b67.x; ov2[7] = b67.y;
    }
    #pragma unroll
    for (int f = 0; f < 16; f++) {
        unsigned long long a0 = splat2(xw[f]);
        unsigned long long a1 = splat2(u1w[f]);
        unsigned long long a2 = splat2(u2w[f]);
        const ulonglong2* g0 = (const ulonglong2*)&sG[0][f][0];
        const ulonglong2* g1 = (const ulonglong2*)&sG[1][f][0];
        const ulonglong2* g2 = (const ulonglong2*)&sG[2][f][0];
        ulonglong2 r0A = g0[0], r0B = g0[1], r0C = g0[2], r0D = g0[3];
        ulonglong2 r1A = g1[0], r1B = g1[1], r1C = g1[2], r1D = g1[3];
        ulonglong2 r2A = g2[0], r2B = g2[1], r2C = g2[2], r2D = g2[3];
        fma2(ov2[0], a0, r0A.x); fma2(ov2[1], a0, r0A.y);
        fma2(ov2[2], a0, r0B.x); fma2(ov2[3], a0, r0B.y);
        fma2(ov2[4], a0, r0C.x); fma2(ov2[5], a0, r0C.y);
        fma2(ov2[6], a0, r0D.x); fma2(ov2[7], a0, r0D.y);
        fma2(ov2[0], a1, r1A.x); fma2(ov2[1], a1, r1A.y);
        fma2(ov2[2], a1, r1B.x); fma2(ov2[3], a1, r1B.y);
        fma2(ov2[4], a1, r1C.x); fma2(ov2[5], a1, r1C.y);
        fma2(ov2[6], a1, r1D.x); fma2(ov2[7], a1, r1D.y);
        fma2(ov2[0], a2, r2A.x); fma2(ov2[1], a2, r2A.y);
        fma2(ov2[2], a2, r2B.x); fma2(ov2[3], a2, r2B.y);
        fma2(ov2[4], a2, r2C.x); fma2(ov2[5], a2, r2C.y);
        fma2(ov2[6], a2, r2D.x); fma2(ov2[7], a2, r2D.y);
    }

    ulonglong2* ob = (ulonglong2*)(out + (size_t)blockIdx.x * 2048 + t * 16);
    ulonglong2 s0, s1, s2, s3;
    s0.x = ov2[0]; s0.y = ov2[1];
    s1.x = ov2[2]; s1.y = ov2[3];
    s2.x = ov2[4]; s2.y = ov2[5];
    s3.x = ov2[6]; s3.y = ov2[7];
    ob[0] = s0; ob[1] = s1; ob[2] = s2; ob[3] = s3;
}

extern "C" void kernel_launch(void* const* d_in, const int* in_sizes, int n_in,
                              void* d_out, int out_size) {
    const float* x      = (const float*)d_in[0];  // [1024,128,16]
    const float* weight = (const float*)d_in[1];  // [3,16,16]
    const float* bias   = (const float*)d_in[2];  // [16]
    const float* adj    = (const float*)d_in[3];  // [16,16]
    int batch = in_sizes[0] / (T_LEN * F_DIM);

    setup_kernel<<<1, 512>>>(adj, weight);
    sgconv_main_kernel<<<batch, 128>>>(x, bias, (float*)d_out);
}